// round 11
// baseline (speedup 1.0000x reference)
#include <cuda_runtime.h>

// ---------------------------------------------------------------------------
// DeepGRL 3-layer GCN on GB300.
// fused(GEMM1 || degree) -> scanAC(grid-sync prefix+dinv+zero fill) ->
//   scatter(x2) -> agg1 -> GEMM2(*dinv) -> agg2(folded) -> GEMM3(*dinv) ->
//   agg3(folded) -> out.   8 launches.
// Invariants restored per call: g_fill==0, g_stsum/g_stsq==0, g_c1==g_c2==0.
// ---------------------------------------------------------------------------

#define N_ 50000
#define E_ 600000
#define NB_ 196          // scan blocks: 196*256 >= N_
#define GB_ 391          // GEMM blocks for BM=128
#define EB_ 2344         // 1-edge/thread blocks
#define EB2_ 1172        // 2-edge/thread blocks

typedef unsigned long long ull;

__device__ __align__(16) int   g_fill[NB_ * 256];    // zero at call start
__device__ __align__(16) int   g_part[NB_];
__device__ __align__(16) int   g_rp[N_ + 1];
__device__ __align__(16) int   g_col[E_];
__device__ __align__(16) float g_dinv[N_];
__device__ __align__(16) float g_h1[(size_t)N_ * 128];
__device__ __align__(16) float g_h2[(size_t)N_ * 128];
__device__ __align__(16) float g_stsum[2][128];      // zero at call start
__device__ __align__(16) float g_stsq[2][128];
__device__ int g_c1, g_c2;                           // scanAC epoch counters

// ---------------------------------------------------------------------------
__device__ __forceinline__ int probe_is64(const int* __restrict__ w, int tid) {
    __shared__ int s_or;
    if (tid == 0) s_or = 0;
    __syncthreads();
    int v = w[2 * tid + 1] | w[2 * (tid + 256) + 1];
    if (__any_sync(0xffffffffu, v != 0) && (tid & 31) == 0) atomicOr(&s_or, 1);
    __syncthreads();
    return s_or == 0;
}

__device__ __forceinline__ int edge_at(const void* ei, int is64, long long idx) {
    if (is64) return (int)((const long long*)ei)[idx];
    return ((const int*)ei)[idx];
}

// ---------------------------------------------------------------------------
__device__ __forceinline__ void ffma2(ull &d, ull a, ull b) {
    asm("fma.rn.f32x2 %0, %1, %2, %0;" : "+l"(d) : "l"(a), "l"(b));
}
__device__ __forceinline__ ull dup2(float a) {
    ull r;
    asm("mov.b64 %0, {%1, %1};" : "=l"(r) : "r"(__float_as_uint(a)));
    return r;
}

// GEMM body: C = act(A) @ W; FOLD: scale output row r by dinv[r].
template<int BN, int ACT, int SIDX, int FOLD>
__device__ __forceinline__ void gemm_body(const float* __restrict__ A,
                                          const float* __restrict__ W,
                                          const float* __restrict__ gam,
                                          const float* __restrict__ bet,
                                          int row0) {
    __shared__ float sA[32][136];
    __shared__ float sW[32][BN + 4];
    __shared__ float s_scale[128], s_shift[128];

    float* C = g_h1;
    const int tid = threadIdx.x;

    if (ACT && tid < 128) {
        const float invn = 1.0f / (float)N_;
        float m = g_stsum[SIDX][tid] * invn;
        float v = g_stsq[SIDX][tid] * invn - m * m;
        float sc = gam[tid] * rsqrtf(v + 1e-5f);
        s_scale[tid] = sc;
        s_shift[tid] = bet[tid] - m * sc;
    }
    if (ACT) __syncthreads();

    const int tx = tid & 15, ty = tid >> 4;
    const int NP = BN / 32;

    ull acc[8][NP > 0 ? NP : 1];
    #pragma unroll
    for (int i = 0; i < 8; i++)
        #pragma unroll
        for (int j = 0; j < NP; j++) acc[i][j] = 0ull;

    #pragma unroll
    for (int ks = 0; ks < 4; ks++) {
        const int k0 = ks * 32;

        #pragma unroll
        for (int h = 0; h < 4; h++) {
            int t = tid + h * 256;
            int r = t >> 3;
            int c = (t & 7) * 4;
            float4 v = make_float4(0.f, 0.f, 0.f, 0.f);
            int gr = row0 + r;
            if (gr < N_) v = *(const float4*)(A + (size_t)gr * 128 + k0 + c);
            if (ACT) {
                v.x = fmaxf(fmaf(v.x, s_scale[k0 + c + 0], s_shift[k0 + c + 0]), 0.f);
                v.y = fmaxf(fmaf(v.y, s_scale[k0 + c + 1], s_shift[k0 + c + 1]), 0.f);
                v.z = fmaxf(fmaf(v.z, s_scale[k0 + c + 2], s_shift[k0 + c + 2]), 0.f);
                v.w = fmaxf(fmaf(v.w, s_scale[k0 + c + 3], s_shift[k0 + c + 3]), 0.f);
            }
            sA[c + 0][r] = v.x;
            sA[c + 1][r] = v.y;
            sA[c + 2][r] = v.z;
            sA[c + 3][r] = v.w;
        }

        #pragma unroll
        for (int h = 0; h < (32 * BN / 4) / 256; h++) {
            int t = tid + h * 256;
            int k = t / (BN / 4);
            int c = (t % (BN / 4)) * 4;
            *(float4*)(&sW[k][c]) = *(const float4*)(W + (size_t)(k0 + k) * BN + c);
        }
        __syncthreads();

        #pragma unroll 4
        for (int k = 0; k < 32; k++) {
            float4 a0 = *(const float4*)(&sA[k][ty * 8]);
            float4 a1 = *(const float4*)(&sA[k][ty * 8 + 4]);
            ull av[8];
            av[0] = dup2(a0.x); av[1] = dup2(a0.y);
            av[2] = dup2(a0.z); av[3] = dup2(a0.w);
            av[4] = dup2(a1.x); av[5] = dup2(a1.y);
            av[6] = dup2(a1.z); av[7] = dup2(a1.w);
            ull bv[NP > 0 ? NP : 1];
            #pragma unroll
            for (int j = 0; j < NP; j += 2) {
                ulonglong2 b = *(const ulonglong2*)(&sW[k][tx * (2 * NP) + 2 * j]);
                bv[j] = b.x; bv[j + 1] = b.y;
            }
            #pragma unroll
            for (int i = 0; i < 8; i++)
                #pragma unroll
                for (int j = 0; j < NP; j++)
                    ffma2(acc[i][j], av[i], bv[j]);
        }
        __syncthreads();
    }

    #pragma unroll
    for (int i = 0; i < 8; i++) {
        int r = row0 + ty * 8 + i;
        if (r < N_) {
            float sc = FOLD ? g_dinv[r] : 1.0f;
            #pragma unroll
            for (int j = 0; j < NP; j += 2) {
                float4 v;
                v.x = __uint_as_float((unsigned)(acc[i][j] & 0xffffffffull));
                v.y = __uint_as_float((unsigned)(acc[i][j] >> 32));
                v.z = __uint_as_float((unsigned)(acc[i][j + 1] & 0xffffffffull));
                v.w = __uint_as_float((unsigned)(acc[i][j + 1] >> 32));
                if (FOLD) { v.x *= sc; v.y *= sc; v.z *= sc; v.w *= sc; }
                *(float4*)(C + (size_t)r * BN + tx * (2 * NP) + 2 * j) = v;
            }
        }
    }
}

// ---------------------------------------------------------------------------
// Launch 1: blocks [0,GB_) GEMM1; rest histogram degrees.
__global__ __launch_bounds__(256, 2)
void fused1_kernel(const float* __restrict__ x, const float* __restrict__ W1,
                   const void* __restrict__ ei) {
    if (blockIdx.x < GB_) {
        gemm_body<128, 0, 0, 0>(x, W1, nullptr, nullptr, blockIdx.x * 128);
    } else {
        int is64 = probe_is64((const int*)ei, threadIdx.x);
        int e = (blockIdx.x - GB_) * 256 + threadIdx.x;
        if (e < E_) {
            int d = edge_at(ei, is64, (long long)E_ + e);
            if ((unsigned)d < (unsigned)N_) atomicAdd(&g_fill[d], 1);
        }
    }
}

// scanAC: per-block sums -> grid barrier -> global exclusive prefix; writes
// rp, dinv, zeroes g_fill. Epoch counters self-reset.
__global__ __launch_bounds__(256) void scanAC_kernel() {
    __shared__ int ws[8];
    __shared__ int s_base;
    int t = threadIdx.x;
    int lane = t & 31, w = t >> 5;
    int i = blockIdx.x * 256 + t;
    int v = (i < N_) ? g_fill[i] : 0;

    // block sum -> g_part[bid]
    {
        int x = v;
        #pragma unroll
        for (int o = 16; o > 0; o >>= 1) x += __shfl_down_sync(0xffffffffu, x, o);
        if (lane == 0) ws[w] = x;
        __syncthreads();
        if (t == 0) {
            int b = 0;
            #pragma unroll
            for (int k = 0; k < 8; k++) b += ws[k];
            g_part[blockIdx.x] = b;
            __threadfence();
            atomicAdd(&g_c1, 1);
            while (*(volatile int*)&g_c1 < NB_) { }
        }
        __syncthreads();
        __threadfence();
    }

    // base = sum of partials below this block
    {
        int pv = (t < NB_ && t < (int)blockIdx.x) ? g_part[t] : 0;
        int x = pv;
        #pragma unroll
        for (int o = 16; o > 0; o >>= 1) x += __shfl_down_sync(0xffffffffu, x, o);
        if (lane == 0) ws[w] = x;
        __syncthreads();
        if (t == 0) {
            int b = 0;
            #pragma unroll
            for (int k = 0; k < 8; k++) b += ws[k];
            s_base = b;
        }
        __syncthreads();
    }
    int base = s_base;
    __syncthreads();

    // block-local exclusive scan
    int x = v;
    #pragma unroll
    for (int o = 1; o < 32; o <<= 1) {
        int q = __shfl_up_sync(0xffffffffu, x, o);
        if (lane >= o) x += q;
    }
    if (lane == 31) ws[w] = x;
    __syncthreads();
    if (w == 0 && lane < 8) {
        int y = ws[lane];
        #pragma unroll
        for (int o = 1; o < 8; o <<= 1) {
            int q = __shfl_up_sync(0xffu, y, o);
            if (lane >= o) y += q;
        }
        ws[lane] = y;
    }
    __syncthreads();
    int excl = base + x - v + (w > 0 ? ws[w - 1] : 0);
    if (i < N_) {
        g_rp[i] = excl;
        g_dinv[i] = rsqrtf((float)(v + 1));
        g_fill[i] = 0;
        if (i == N_ - 1) g_rp[N_] = excl + v;
    }

    // epoch cleanup: last block resets both counters
    __syncthreads();
    __threadfence();
    if (t == 0) {
        int o = atomicAdd(&g_c2, 1);
        if (o == NB_ - 1) { g_c1 = 0; g_c2 = 0; __threadfence(); }
    }
}

// scatter: 2 edges per thread, vectorized edge reads.
__global__ void scatter_kernel(const void* __restrict__ ei) {
    int is64 = probe_is64((const int*)ei, threadIdx.x);
    int e = (blockIdx.x * 256 + threadIdx.x) * 2;
    if (e + 1 < E_) {
        int s0, s1, d0, d1;
        if (is64) {
            longlong2 sp = ((const longlong2*)ei)[e >> 1];
            longlong2 dp = ((const longlong2*)ei)[(E_ + e) >> 1];
            s0 = (int)sp.x; s1 = (int)sp.y;
            d0 = (int)dp.x; d1 = (int)dp.y;
        } else {
            int2 sp = ((const int2*)ei)[e >> 1];
            int2 dp = ((const int2*)ei)[(E_ + e) >> 1];
            s0 = sp.x; s1 = sp.y;
            d0 = dp.x; d1 = dp.y;
        }
        if ((unsigned)s0 < (unsigned)N_ && (unsigned)d0 < (unsigned)N_) {
            int pos = g_rp[d0] + atomicAdd(&g_fill[d0], 1);
            if ((unsigned)pos < (unsigned)E_) g_col[pos] = s0;
        }
        if ((unsigned)s1 < (unsigned)N_ && (unsigned)d1 < (unsigned)N_) {
            int pos = g_rp[d1] + atomicAdd(&g_fill[d1], 1);
            if ((unsigned)pos < (unsigned)E_) g_col[pos] = s1;
        }
    } else if (e < E_) {
        int s = edge_at(ei, is64, e);
        int d = edge_at(ei, is64, (long long)E_ + e);
        if ((unsigned)s < (unsigned)N_ && (unsigned)d < (unsigned)N_) {
            int pos = g_rp[d] + atomicAdd(&g_fill[d], 1);
            if ((unsigned)pos < (unsigned)E_) g_col[pos] = s;
        }
    }
}

template<int BN, int ACT, int SIDX, int FOLD>
__global__ __launch_bounds__(256, 2)
void gemm_kernel(const float* __restrict__ W,
                 const float* __restrict__ gam, const float* __restrict__ bet) {
    gemm_body<BN, ACT, SIDX, FOLD>((const float*)g_h2, W, gam, bet, blockIdx.x * 128);
}

// ---------------------------------------------------------------------------
// Gather aggregation. FOLD=0: u = dinv[col]*dinv[row] per edge (layer 1).
// FOLD=1: h rows pre-scaled by dinv; acc = h'[row] + sum h'[col]; out =
// dinv_row*acc + bias. CLEAN: 1 zero stats[0], 2 zero stats[1] + g_fill.
// ---------------------------------------------------------------------------
template<int F, int STATS, int SIDX, int OUTP, int CLEAN, int FOLD>
__global__ __launch_bounds__(256)
void agg_kernel(const float* __restrict__ bias, float* __restrict__ outp) {
    __shared__ float s_sum[128], s_sq[128];
    const float* __restrict__ h = g_h1;
    const float* __restrict__ dv = g_dinv;
    const int* __restrict__ cols = g_col;
    float* out = (OUTP == 0) ? g_h2 : outp;
    int tid = threadIdx.x;
    if (STATS) {
        if (tid < 128) { s_sum[tid] = 0.f; s_sq[tid] = 0.f; }
        __syncthreads();
    }
    if (CLEAN == 1 && blockIdx.x == 0 && tid < 128) {
        g_stsum[0][tid] = 0.f; g_stsq[0][tid] = 0.f;
    }
    if (CLEAN == 2 && blockIdx.x == 0 && tid < 128) {
        g_stsum[1][tid] = 0.f; g_stsq[1][tid] = 0.f;
    }
    int lane = tid & 31;
    int gw = (blockIdx.x * 256 + tid) >> 5;
    int nw = (gridDim.x * 256) >> 5;

    if (F == 128) {
        float4 bv = *(const float4*)(bias + lane * 4);
        for (int row = gw; row < N_; row += nw) {
            float dr = dv[row];
            if (CLEAN == 2 && lane == 0) g_fill[row] = 0;
            float4 a = *(const float4*)(h + (size_t)row * 128 + lane * 4);
            float4 acc;
            if (FOLD) { acc = a; }
            else {
                float w0 = dr * dr;
                acc.x = w0 * a.x; acc.y = w0 * a.y; acc.z = w0 * a.z; acc.w = w0 * a.w;
            }
            int p = g_rp[row], pe = g_rp[row + 1];
            for (; p + 8 <= pe; p += 8) {
                int c[8];
                #pragma unroll
                for (int q = 0; q < 8; q++) c[q] = cols[p + q];
                float4 hv[8];
                #pragma unroll
                for (int q = 0; q < 8; q++)
                    hv[q] = *(const float4*)(h + (size_t)c[q] * 128 + lane * 4);
                if (FOLD) {
                    #pragma unroll
                    for (int q = 0; q < 8; q++) {
                        acc.x += hv[q].x; acc.y += hv[q].y;
                        acc.z += hv[q].z; acc.w += hv[q].w;
                    }
                } else {
                    #pragma unroll
                    for (int q = 0; q < 8; q++) {
                        float u = dv[c[q]] * dr;
                        acc.x = fmaf(u, hv[q].x, acc.x); acc.y = fmaf(u, hv[q].y, acc.y);
                        acc.z = fmaf(u, hv[q].z, acc.z); acc.w = fmaf(u, hv[q].w, acc.w);
                    }
                }
            }
            for (; p < pe; p++) {
                int c0 = cols[p];
                float4 h0 = *(const float4*)(h + (size_t)c0 * 128 + lane * 4);
                if (FOLD) {
                    acc.x += h0.x; acc.y += h0.y; acc.z += h0.z; acc.w += h0.w;
                } else {
                    float u0 = dv[c0] * dr;
                    acc.x = fmaf(u0, h0.x, acc.x); acc.y = fmaf(u0, h0.y, acc.y);
                    acc.z = fmaf(u0, h0.z, acc.z); acc.w = fmaf(u0, h0.w, acc.w);
                }
            }
            if (FOLD) {
                acc.x = fmaf(dr, acc.x, bv.x); acc.y = fmaf(dr, acc.y, bv.y);
                acc.z = fmaf(dr, acc.z, bv.z); acc.w = fmaf(dr, acc.w, bv.w);
            } else {
                acc.x += bv.x; acc.y += bv.y; acc.z += bv.z; acc.w += bv.w;
            }
            *(float4*)(out + (size_t)row * 128 + lane * 4) = acc;
            if (STATS) {
                int cc = lane * 4;
                atomicAdd(&s_sum[cc + 0], acc.x); atomicAdd(&s_sq[cc + 0], acc.x * acc.x);
                atomicAdd(&s_sum[cc + 1], acc.y); atomicAdd(&s_sq[cc + 1], acc.y * acc.y);
                atomicAdd(&s_sum[cc + 2], acc.z); atomicAdd(&s_sq[cc + 2], acc.z * acc.z);
                atomicAdd(&s_sum[cc + 3], acc.w); atomicAdd(&s_sq[cc + 3], acc.w * acc.w);
            }
        }
        if (STATS) {
            __syncthreads();
            if (tid < 128) {
                atomicAdd(&g_stsum[SIDX][tid], s_sum[tid]);
                atomicAdd(&g_stsq[SIDX][tid], s_sq[tid]);
            }
        }
    } else {  // F == 64
        float2 bv = *(const float2*)(bias + lane * 2);
        for (int row = gw; row < N_; row += nw) {
            float dr = dv[row];
            if (CLEAN == 2 && lane == 0) g_fill[row] = 0;
            float2 a = *(const float2*)(h + (size_t)row * 64 + lane * 2);
            float2 acc;
            if (FOLD) { acc = a; }
            else { float w0 = dr * dr; acc.x = w0 * a.x; acc.y = w0 * a.y; }
            int p = g_rp[row], pe = g_rp[row + 1];
            for (; p + 4 <= pe; p += 4) {
                int c0 = cols[p], c1 = cols[p + 1], c2 = cols[p + 2], c3 = cols[p + 3];
                float2 h0 = *(const float2*)(h + (size_t)c0 * 64 + lane * 2);
                float2 h1 = *(const float2*)(h + (size_t)c1 * 64 + lane * 2);
                float2 h2 = *(const float2*)(h + (size_t)c2 * 64 + lane * 2);
                float2 h3 = *(const float2*)(h + (size_t)c3 * 64 + lane * 2);
                if (FOLD) {
                    acc.x += h0.x + h1.x + h2.x + h3.x;
                    acc.y += h0.y + h1.y + h2.y + h3.y;
                } else {
                    float u0 = dv[c0] * dr, u1 = dv[c1] * dr;
                    float u2 = dv[c2] * dr, u3 = dv[c3] * dr;
                    acc.x = fmaf(u0, h0.x, acc.x); acc.y = fmaf(u0, h0.y, acc.y);
                    acc.x = fmaf(u1, h1.x, acc.x); acc.y = fmaf(u1, h1.y, acc.y);
                    acc.x = fmaf(u2, h2.x, acc.x); acc.y = fmaf(u2, h2.y, acc.y);
                    acc.x = fmaf(u3, h3.x, acc.x); acc.y = fmaf(u3, h3.y, acc.y);
                }
            }
            for (; p < pe; p++) {
                int c0 = cols[p];
                float2 h0 = *(const float2*)(h + (size_t)c0 * 64 + lane * 2);
                if (FOLD) { acc.x += h0.x; acc.y += h0.y; }
                else {
                    float u0 = dv[c0] * dr;
                    acc.x = fmaf(u0, h0.x, acc.x); acc.y = fmaf(u0, h0.y, acc.y);
                }
            }
            if (FOLD) {
                acc.x = fmaf(dr, acc.x, bv.x); acc.y = fmaf(dr, acc.y, bv.y);
            } else {
                acc.x += bv.x; acc.y += bv.y;
            }
            *(float2*)(out + (size_t)row * 64 + lane * 2) = acc;
        }
    }
}

// ---------------------------------------------------------------------------
extern "C" void kernel_launch(void* const* d_in, const int* in_sizes, int n_in,
                              void* d_out, int out_size) {
    const float* x   = (const float*)d_in[0];
    const void*  ei  = d_in[1];
    const float* W1  = (const float*)d_in[2];
    const float* b1  = (const float*)d_in[3];
    const float* g1  = (const float*)d_in[4];
    const float* be1 = (const float*)d_in[5];
    const float* W2  = (const float*)d_in[6];
    const float* b2  = (const float*)d_in[7];
    const float* g2  = (const float*)d_in[8];
    const float* be2 = (const float*)d_in[9];
    const float* W3  = (const float*)d_in[10];
    const float* b3  = (const float*)d_in[11];
    float*       out = (float*)d_out;

    const int ab = 1184;

    fused1_kernel<<<GB_ + EB_, 256>>>(x, W1, ei);      // GEMM1 || degree
    scanAC_kernel<<<NB_, 256>>>();
    scatter_kernel<<<EB2_, 256>>>(ei);

    agg_kernel<128, 1, 0, 0, 0, 0><<<ab, 256>>>(b1, nullptr);
    gemm_kernel<128, 1, 0, 1><<<GB_, 256>>>(W2, g1, be1);
    agg_kernel<128, 1, 1, 0, 1, 1><<<ab, 256>>>(b2, nullptr);
    gemm_kernel<64, 1, 1, 1><<<GB_, 256>>>(W3, g2, be2);
    agg_kernel<64, 0, 0, 1, 2, 1><<<ab, 256>>>(b3, out);
}

// round 13
// speedup vs baseline: 1.0910x; 1.0910x over previous
#include <cuda_runtime.h>

// ---------------------------------------------------------------------------
// DeepGRL 3-layer GCN on GB300.
// fused(GEMM1 || degree) -> scanAC(grid-sync prefix+dinv+zero fill) ->
//   scatter(x2) -> agg1 -> GEMM2(*dinv) -> agg2(folded) -> GEMM3(*dinv) ->
//   agg3(folded) -> out.   8 launches.
// agg F=128 uses half-row virtual rows (float2/lane) for 2x gather MLP.
// Invariants restored per call: g_fill==0, g_stsum/g_stsq==0, g_c1==g_c2==0.
// ---------------------------------------------------------------------------

#define N_ 50000
#define E_ 600000
#define NB_ 196          // scan blocks: 196*256 >= N_
#define GB_ 391          // GEMM blocks for BM=128
#define EB_ 2344         // 1-edge/thread blocks
#define EB2_ 1172        // 2-edge/thread blocks

typedef unsigned long long ull;

__device__ __align__(16) int   g_fill[NB_ * 256];    // zero at call start
__device__ __align__(16) int   g_part[NB_];
__device__ __align__(16) int   g_rp[N_ + 1];
__device__ __align__(16) int   g_col[E_];
__device__ __align__(16) float g_dinv[N_];
__device__ __align__(16) float g_h1[(size_t)N_ * 128];
__device__ __align__(16) float g_h2[(size_t)N_ * 128];
__device__ __align__(16) float g_stsum[2][128];      // zero at call start
__device__ __align__(16) float g_stsq[2][128];
__device__ int g_c1, g_c2;                           // scanAC epoch counters

// ---------------------------------------------------------------------------
__device__ __forceinline__ int probe_is64(const int* __restrict__ w, int tid) {
    __shared__ int s_or;
    if (tid == 0) s_or = 0;
    __syncthreads();
    int v = w[2 * tid + 1] | w[2 * (tid + 256) + 1];
    if (__any_sync(0xffffffffu, v != 0) && (tid & 31) == 0) atomicOr(&s_or, 1);
    __syncthreads();
    return s_or == 0;
}

__device__ __forceinline__ int edge_at(const void* ei, int is64, long long idx) {
    if (is64) return (int)((const long long*)ei)[idx];
    return ((const int*)ei)[idx];
}

// ---------------------------------------------------------------------------
__device__ __forceinline__ void ffma2(ull &d, ull a, ull b) {
    asm("fma.rn.f32x2 %0, %1, %2, %0;" : "+l"(d) : "l"(a), "l"(b));
}
__device__ __forceinline__ ull dup2(float a) {
    ull r;
    asm("mov.b64 %0, {%1, %1};" : "=l"(r) : "r"(__float_as_uint(a)));
    return r;
}

// GEMM body: C = act(A) @ W; FOLD: scale output row r by dinv[r].
template<int BN, int ACT, int SIDX, int FOLD>
__device__ __forceinline__ void gemm_body(const float* __restrict__ A,
                                          const float* __restrict__ W,
                                          const float* __restrict__ gam,
                                          const float* __restrict__ bet,
                                          int row0) {
    __shared__ float sA[32][136];
    __shared__ float sW[32][BN + 4];
    __shared__ float s_scale[128], s_shift[128];

    float* C = g_h1;
    const int tid = threadIdx.x;

    if (ACT && tid < 128) {
        const float invn = 1.0f / (float)N_;
        float m = g_stsum[SIDX][tid] * invn;
        float v = g_stsq[SIDX][tid] * invn - m * m;
        float sc = gam[tid] * rsqrtf(v + 1e-5f);
        s_scale[tid] = sc;
        s_shift[tid] = bet[tid] - m * sc;
    }
    if (ACT) __syncthreads();

    const int tx = tid & 15, ty = tid >> 4;
    const int NP = BN / 32;

    ull acc[8][NP > 0 ? NP : 1];
    #pragma unroll
    for (int i = 0; i < 8; i++)
        #pragma unroll
        for (int j = 0; j < NP; j++) acc[i][j] = 0ull;

    #pragma unroll
    for (int ks = 0; ks < 4; ks++) {
        const int k0 = ks * 32;

        #pragma unroll
        for (int h = 0; h < 4; h++) {
            int t = tid + h * 256;
            int r = t >> 3;
            int c = (t & 7) * 4;
            float4 v = make_float4(0.f, 0.f, 0.f, 0.f);
            int gr = row0 + r;
            if (gr < N_) v = *(const float4*)(A + (size_t)gr * 128 + k0 + c);
            if (ACT) {
                v.x = fmaxf(fmaf(v.x, s_scale[k0 + c + 0], s_shift[k0 + c + 0]), 0.f);
                v.y = fmaxf(fmaf(v.y, s_scale[k0 + c + 1], s_shift[k0 + c + 1]), 0.f);
                v.z = fmaxf(fmaf(v.z, s_scale[k0 + c + 2], s_shift[k0 + c + 2]), 0.f);
                v.w = fmaxf(fmaf(v.w, s_scale[k0 + c + 3], s_shift[k0 + c + 3]), 0.f);
            }
            sA[c + 0][r] = v.x;
            sA[c + 1][r] = v.y;
            sA[c + 2][r] = v.z;
            sA[c + 3][r] = v.w;
        }

        #pragma unroll
        for (int h = 0; h < (32 * BN / 4) / 256; h++) {
            int t = tid + h * 256;
            int k = t / (BN / 4);
            int c = (t % (BN / 4)) * 4;
            *(float4*)(&sW[k][c]) = *(const float4*)(W + (size_t)(k0 + k) * BN + c);
        }
        __syncthreads();

        #pragma unroll 4
        for (int k = 0; k < 32; k++) {
            float4 a0 = *(const float4*)(&sA[k][ty * 8]);
            float4 a1 = *(const float4*)(&sA[k][ty * 8 + 4]);
            ull av[8];
            av[0] = dup2(a0.x); av[1] = dup2(a0.y);
            av[2] = dup2(a0.z); av[3] = dup2(a0.w);
            av[4] = dup2(a1.x); av[5] = dup2(a1.y);
            av[6] = dup2(a1.z); av[7] = dup2(a1.w);
            ull bv[NP > 0 ? NP : 1];
            #pragma unroll
            for (int j = 0; j < NP; j += 2) {
                ulonglong2 b = *(const ulonglong2*)(&sW[k][tx * (2 * NP) + 2 * j]);
                bv[j] = b.x; bv[j + 1] = b.y;
            }
            #pragma unroll
            for (int i = 0; i < 8; i++)
                #pragma unroll
                for (int j = 0; j < NP; j++)
                    ffma2(acc[i][j], av[i], bv[j]);
        }
        __syncthreads();
    }

    #pragma unroll
    for (int i = 0; i < 8; i++) {
        int r = row0 + ty * 8 + i;
        if (r < N_) {
            float sc = FOLD ? g_dinv[r] : 1.0f;
            #pragma unroll
            for (int j = 0; j < NP; j += 2) {
                float4 v;
                v.x = __uint_as_float((unsigned)(acc[i][j] & 0xffffffffull));
                v.y = __uint_as_float((unsigned)(acc[i][j] >> 32));
                v.z = __uint_as_float((unsigned)(acc[i][j + 1] & 0xffffffffull));
                v.w = __uint_as_float((unsigned)(acc[i][j + 1] >> 32));
                if (FOLD) { v.x *= sc; v.y *= sc; v.z *= sc; v.w *= sc; }
                *(float4*)(C + (size_t)r * BN + tx * (2 * NP) + 2 * j) = v;
            }
        }
    }
}

// ---------------------------------------------------------------------------
__global__ __launch_bounds__(256, 2)
void fused1_kernel(const float* __restrict__ x, const float* __restrict__ W1,
                   const void* __restrict__ ei) {
    if (blockIdx.x < GB_) {
        gemm_body<128, 0, 0, 0>(x, W1, nullptr, nullptr, blockIdx.x * 128);
    } else {
        int is64 = probe_is64((const int*)ei, threadIdx.x);
        int e = (blockIdx.x - GB_) * 256 + threadIdx.x;
        if (e < E_) {
            int d = edge_at(ei, is64, (long long)E_ + e);
            if ((unsigned)d < (unsigned)N_) atomicAdd(&g_fill[d], 1);
        }
    }
}

// scanAC: per-block sums -> grid spin barrier -> global exclusive prefix;
// writes rp, dinv, zeroes g_fill. Epoch counters self-reset.
__global__ __launch_bounds__(256) void scanAC_kernel() {
    __shared__ int ws[8];
    __shared__ int s_base;
    int t = threadIdx.x;
    int lane = t & 31, w = t >> 5;
    int i = blockIdx.x * 256 + t;
    int v = (i < N_) ? g_fill[i] : 0;

    {
        int x = v;
        #pragma unroll
        for (int o = 16; o > 0; o >>= 1) x += __shfl_down_sync(0xffffffffu, x, o);
        if (lane == 0) ws[w] = x;
        __syncthreads();
        if (t == 0) {
            int b = 0;
            #pragma unroll
            for (int k = 0; k < 8; k++) b += ws[k];
            g_part[blockIdx.x] = b;
            __threadfence();
            atomicAdd(&g_c1, 1);
            while (*(volatile int*)&g_c1 < NB_) { }
        }
        __syncthreads();
        __threadfence();
    }

    {
        int pv = (t < NB_ && t < (int)blockIdx.x) ? g_part[t] : 0;
        int x = pv;
        #pragma unroll
        for (int o = 16; o > 0; o >>= 1) x += __shfl_down_sync(0xffffffffu, x, o);
        if (lane == 0) ws[w] = x;
        __syncthreads();
        if (t == 0) {
            int b = 0;
            #pragma unroll
            for (int k = 0; k < 8; k++) b += ws[k];
            s_base = b;
        }
        __syncthreads();
    }
    int base = s_base;
    __syncthreads();

    int x = v;
    #pragma unroll
    for (int o = 1; o < 32; o <<= 1) {
        int q = __shfl_up_sync(0xffffffffu, x, o);
        if (lane >= o) x += q;
    }
    if (lane == 31) ws[w] = x;
    __syncthreads();
    if (w == 0 && lane < 8) {
        int y = ws[lane];
        #pragma unroll
        for (int o = 1; o < 8; o <<= 1) {
            int q = __shfl_up_sync(0xffu, y, o);
            if (lane >= o) y += q;
        }
        ws[lane] = y;
    }
    __syncthreads();
    int excl = base + x - v + (w > 0 ? ws[w - 1] : 0);
    if (i < N_) {
        g_rp[i] = excl;
        g_dinv[i] = rsqrtf((float)(v + 1));
        g_fill[i] = 0;
        if (i == N_ - 1) g_rp[N_] = excl + v;
    }

    __syncthreads();
    __threadfence();
    if (t == 0) {
        int o = atomicAdd(&g_c2, 1);
        if (o == NB_ - 1) { g_c1 = 0; g_c2 = 0; __threadfence(); }
    }
}

__global__ void scatter_kernel(const void* __restrict__ ei) {
    int is64 = probe_is64((const int*)ei, threadIdx.x);
    int e = (blockIdx.x * 256 + threadIdx.x) * 2;
    if (e + 1 < E_) {
        int s0, s1, d0, d1;
        if (is64) {
            longlong2 sp = ((const longlong2*)ei)[e >> 1];
            longlong2 dp = ((const longlong2*)ei)[(E_ + e) >> 1];
            s0 = (int)sp.x; s1 = (int)sp.y;
            d0 = (int)dp.x; d1 = (int)dp.y;
        } else {
            int2 sp = ((const int2*)ei)[e >> 1];
            int2 dp = ((const int2*)ei)[(E_ + e) >> 1];
            s0 = sp.x; s1 = sp.y;
            d0 = dp.x; d1 = dp.y;
        }
        if ((unsigned)s0 < (unsigned)N_ && (unsigned)d0 < (unsigned)N_) {
            int pos = g_rp[d0] + atomicAdd(&g_fill[d0], 1);
            if ((unsigned)pos < (unsigned)E_) g_col[pos] = s0;
        }
        if ((unsigned)s1 < (unsigned)N_ && (unsigned)d1 < (unsigned)N_) {
            int pos = g_rp[d1] + atomicAdd(&g_fill[d1], 1);
            if ((unsigned)pos < (unsigned)E_) g_col[pos] = s1;
        }
    } else if (e < E_) {
        int s = edge_at(ei, is64, e);
        int d = edge_at(ei, is64, (long long)E_ + e);
        if ((unsigned)s < (unsigned)N_ && (unsigned)d < (unsigned)N_) {
            int pos = g_rp[d] + atomicAdd(&g_fill[d], 1);
            if ((unsigned)pos < (unsigned)E_) g_col[pos] = s;
        }
    }
}

template<int BN, int ACT, int SIDX, int FOLD>
__global__ __launch_bounds__(256, 2)
void gemm_kernel(const float* __restrict__ W,
                 const float* __restrict__ gam, const float* __restrict__ bet) {
    gemm_body<BN, ACT, SIDX, FOLD>((const float*)g_h2, W, gam, bet, blockIdx.x * 128);
}

// ---------------------------------------------------------------------------
// Gather aggregation. F=128: half-row virtual rows (float2/lane, 2x MLP).
// FOLD=0: u = dinv[col]*dinv[row] per edge. FOLD=1: h pre-scaled by dinv;
// out = dinv_row * (h'[row] + sum h'[col]) + bias.
// CLEAN: 1 zero stats[0], 2 zero stats[1] + g_fill.
// ---------------------------------------------------------------------------
template<int F, int STATS, int SIDX, int OUTP, int CLEAN, int FOLD>
__global__ __launch_bounds__(256)
void agg_kernel(const float* __restrict__ bias, float* __restrict__ outp) {
    __shared__ float s_sum[128], s_sq[128];
    const float* __restrict__ h = g_h1;
    const float* __restrict__ dv = g_dinv;
    const int* __restrict__ cols = g_col;
    float* out = (OUTP == 0) ? g_h2 : outp;
    int tid = threadIdx.x;
    if (STATS) {
        if (tid < 128) { s_sum[tid] = 0.f; s_sq[tid] = 0.f; }
        __syncthreads();
    }
    if (CLEAN == 1 && blockIdx.x == 0 && tid < 128) {
        g_stsum[0][tid] = 0.f; g_stsq[0][tid] = 0.f;
    }
    if (CLEAN == 2 && blockIdx.x == 0 && tid < 128) {
        g_stsum[1][tid] = 0.f; g_stsq[1][tid] = 0.f;
    }
    int lane = tid & 31;
    int gw = (blockIdx.x * 256 + tid) >> 5;
    int nw = (gridDim.x * 256) >> 5;

    if (F == 128) {
        // virtual rows: vr = row*2 + half; each warp covers 64 features.
        for (int vr = gw; vr < 2 * N_; vr += nw) {
            int row = vr >> 1;
            int half = vr & 1;
            int fo = half * 64 + lane * 2;                 // feature offset
            const float* hb = h + fo;
            float dr = dv[row];
            if (CLEAN == 2 && half == 0 && lane == 0) g_fill[row] = 0;
            float2 bv = *(const float2*)(bias + fo);
            float2 a = *(const float2*)(hb + (size_t)row * 128);
            float2 acc;
            if (FOLD) { acc = a; }
            else { float w0 = dr * dr; acc.x = w0 * a.x; acc.y = w0 * a.y; }
            int p = g_rp[row], pe = g_rp[row + 1];
            for (; p + 8 <= pe; p += 8) {
                int c[8];
                #pragma unroll
                for (int q = 0; q < 8; q++) c[q] = cols[p + q];
                float2 hv[8];
                #pragma unroll
                for (int q = 0; q < 8; q++)
                    hv[q] = *(const float2*)(hb + (size_t)c[q] * 128);
                if (FOLD) {
                    #pragma unroll
                    for (int q = 0; q < 8; q++) { acc.x += hv[q].x; acc.y += hv[q].y; }
                } else {
                    #pragma unroll
                    for (int q = 0; q < 8; q++) {
                        float u = dv[c[q]] * dr;
                        acc.x = fmaf(u, hv[q].x, acc.x);
                        acc.y = fmaf(u, hv[q].y, acc.y);
                    }
                }
            }
            for (; p < pe; p++) {
                int c0 = cols[p];
                float2 h0 = *(const float2*)(hb + (size_t)c0 * 128);
                if (FOLD) { acc.x += h0.x; acc.y += h0.y; }
                else {
                    float u0 = dv[c0] * dr;
                    acc.x = fmaf(u0, h0.x, acc.x); acc.y = fmaf(u0, h0.y, acc.y);
                }
            }
            if (FOLD) {
                acc.x = fmaf(dr, acc.x, bv.x); acc.y = fmaf(dr, acc.y, bv.y);
            } else {
                acc.x += bv.x; acc.y += bv.y;
            }
            *(float2*)(out + (size_t)row * 128 + fo) = acc;
            if (STATS) {
                atomicAdd(&s_sum[fo + 0], acc.x); atomicAdd(&s_sq[fo + 0], acc.x * acc.x);
                atomicAdd(&s_sum[fo + 1], acc.y); atomicAdd(&s_sq[fo + 1], acc.y * acc.y);
            }
        }
        if (STATS) {
            __syncthreads();
            if (tid < 128) {
                atomicAdd(&g_stsum[SIDX][tid], s_sum[tid]);
                atomicAdd(&g_stsq[SIDX][tid], s_sq[tid]);
            }
        }
    } else {  // F == 64, warp per row
        float2 bv = *(const float2*)(bias + lane * 2);
        for (int row = gw; row < N_; row += nw) {
            float dr = dv[row];
            if (CLEAN == 2 && lane == 0) g_fill[row] = 0;
            float2 a = *(const float2*)(h + (size_t)row * 64 + lane * 2);
            float2 acc;
            if (FOLD) { acc = a; }
            else { float w0 = dr * dr; acc.x = w0 * a.x; acc.y = w0 * a.y; }
            int p = g_rp[row], pe = g_rp[row + 1];
            for (; p + 8 <= pe; p += 8) {
                int c[8];
                #pragma unroll
                for (int q = 0; q < 8; q++) c[q] = cols[p + q];
                float2 hv[8];
                #pragma unroll
                for (int q = 0; q < 8; q++)
                    hv[q] = *(const float2*)(h + (size_t)c[q] * 64 + lane * 2);
                if (FOLD) {
                    #pragma unroll
                    for (int q = 0; q < 8; q++) { acc.x += hv[q].x; acc.y += hv[q].y; }
                } else {
                    #pragma unroll
                    for (int q = 0; q < 8; q++) {
                        float u = dv[c[q]] * dr;
                        acc.x = fmaf(u, hv[q].x, acc.x);
                        acc.y = fmaf(u, hv[q].y, acc.y);
                    }
                }
            }
            for (; p < pe; p++) {
                int c0 = cols[p];
                float2 h0 = *(const float2*)(h + (size_t)c0 * 64 + lane * 2);
                if (FOLD) { acc.x += h0.x; acc.y += h0.y; }
                else {
                    float u0 = dv[c0] * dr;
                    acc.x = fmaf(u0, h0.x, acc.x); acc.y = fmaf(u0, h0.y, acc.y);
                }
            }
            if (FOLD) {
                acc.x = fmaf(dr, acc.x, bv.x); acc.y = fmaf(dr, acc.y, bv.y);
            } else {
                acc.x += bv.x; acc.y += bv.y;
            }
            *(float2*)(out + (size_t)row * 64 + lane * 2) = acc;
        }
    }
}

// ---------------------------------------------------------------------------
extern "C" void kernel_launch(void* const* d_in, const int* in_sizes, int n_in,
                              void* d_out, int out_size) {
    const float* x   = (const float*)d_in[0];
    const void*  ei  = d_in[1];
    const float* W1  = (const float*)d_in[2];
    const float* b1  = (const float*)d_in[3];
    const float* g1  = (const float*)d_in[4];
    const float* be1 = (const float*)d_in[5];
    const float* W2  = (const float*)d_in[6];
    const float* b2  = (const float*)d_in[7];
    const float* g2  = (const float*)d_in[8];
    const float* be2 = (const float*)d_in[9];
    const float* W3  = (const float*)d_in[10];
    const float* b3  = (const float*)d_in[11];
    float*       out = (float*)d_out;

    const int ab = 1184;

    fused1_kernel<<<GB_ + EB_, 256>>>(x, W1, ei);      // GEMM1 || degree
    scanAC_kernel<<<NB_, 256>>>();
    scatter_kernel<<<EB2_, 256>>>(ei);

    agg_kernel<128, 1, 0, 0, 0, 0><<<ab, 256>>>(b1, nullptr);
    gemm_kernel<128, 1, 0, 1><<<GB_, 256>>>(W2, g1, be1);
    agg_kernel<128, 1, 1, 0, 1, 1><<<ab, 256>>>(b2, nullptr);
    gemm_kernel<64, 1, 1, 1><<<GB_, 256>>>(W3, g2, be2);
    agg_kernel<64, 0, 0, 1, 2, 1><<<ab, 256>>>(b3, out);
}